// round 13
// baseline (speedup 1.0000x reference)
#include <cuda_runtime.h>
#include <cstdint>
#include <math.h>

// Problem dims
#define BATCH 2
#define SEQ   2048
#define DIM   1024
#define HEADS 8
#define DH    128
#define BH    (BATCH*HEADS)          // 16
#define ROWS  (BATCH*SEQ)            // 4096
#define QKVC  (3*HEADS*DH)           // 3072

// Output packing offsets (out, new_kv, new_norm concatenated)
#define OUT_OFF  0L
#define NKV_OFF  ((long)ROWS*DIM)
#define NNORM_OFF (NKV_OFF + (long)BH*DH*DH)

// ---------------- device scratch (allocation-free) ----------------
__device__ float g_xn[ROWS*DIM];
__device__ float g_qkv[(long)ROWS*QKVC];
__device__ float g_q [BH*SEQ*DH];
__device__ float g_k [BH*SEQ*DH];
__device__ float g_v [BH*SEQ*DH];
__device__ float g_qe[BH*SEQ*DH];
__device__ float g_ke[BH*SEQ*DH];
__device__ float g_vp[BH*SEQ*DH];
__device__ float g_att[BH*SEQ*DH];
__device__ float g_mo[BH*SEQ*DH];
__device__ float g_dv[BH*SEQ*DH];
__device__ float g_comb[ROWS*DIM];
__device__ float g_nkv_part[16*BH*DH*DH];
__device__ float g_nn_part[BH*16*DH];
__device__ float g_freq[64];

// ---------------- tf32 helpers ----------------
__device__ __forceinline__ uint32_t f2tf(float x) {
    uint32_t r;
    asm("cvt.rna.tf32.f32 %0, %1;" : "=r"(r) : "f"(x));
    return r;
}
__device__ __forceinline__ void mma_tf32(float* c, const uint32_t* a,
                                         uint32_t b0, uint32_t b1) {
    asm volatile(
        "mma.sync.aligned.m16n8k8.row.col.f32.tf32.tf32.f32 "
        "{%0,%1,%2,%3}, {%4,%5,%6,%7}, {%8,%9}, {%0,%1,%2,%3};"
        : "+f"(c[0]), "+f"(c[1]), "+f"(c[2]), "+f"(c[3])
        : "r"(a[0]), "r"(a[1]), "r"(a[2]), "r"(a[3]), "r"(b0), "r"(b1));
}

#define BM 128
#define BN 128
#define BKT 32
#define BKP 36      // padded k-stride for [rows][k] layouts
#define BNP 132     // padded n-stride for [k][n] layout

// ============ tf32 GEMM NN: C[M,N] = A[M,K] @ B[K,N], row-major ============
__global__ void __launch_bounds__(256)
tfgemm_nn(const float* __restrict__ A, const float* __restrict__ B,
          float* __restrict__ C, int N, int K,
          long sA, long sB, long sC) {
    A += (long)blockIdx.z * sA;
    B += (long)blockIdx.z * sB;
    C += (long)blockIdx.z * sC;
    int by = blockIdx.y, bx = blockIdx.x;

    __shared__ uint32_t As[BM][BKP];
    __shared__ uint32_t Bs[BKT][BNP];

    int tid = threadIdx.x;
    int lane = tid & 31, warp = tid >> 5;
    int gid = lane >> 2, tig = lane & 3;
    int wm = (warp & 1) * 64, wn = (warp >> 1) * 32;

    float acc[4][4][4] = {};
    const float* Ag = A + (long)by*BM*K;
    const float* Bg = B + bx*BN;

    for (int k0 = 0; k0 < K; k0 += BKT) {
        #pragma unroll
        for (int p = 0; p < 4; ++p) {
            int idx = tid + p*256;
            int m = idx >> 3, kq = idx & 7;
            float4 va = *(const float4*)(Ag + (long)m*K + k0 + kq*4);
            As[m][kq*4+0] = f2tf(va.x); As[m][kq*4+1] = f2tf(va.y);
            As[m][kq*4+2] = f2tf(va.z); As[m][kq*4+3] = f2tf(va.w);
        }
        #pragma unroll
        for (int p = 0; p < 4; ++p) {
            int idx = tid + p*256;
            int kk = idx >> 5, nq = idx & 31;
            float4 vb = *(const float4*)(Bg + (long)(k0+kk)*N + nq*4);
            Bs[kk][nq*4+0] = f2tf(vb.x); Bs[kk][nq*4+1] = f2tf(vb.y);
            Bs[kk][nq*4+2] = f2tf(vb.z); Bs[kk][nq*4+3] = f2tf(vb.w);
        }
        __syncthreads();
        #pragma unroll
        for (int ks = 0; ks < BKT; ks += 8) {
            uint32_t af[4][4];
            #pragma unroll
            for (int mi = 0; mi < 4; ++mi) {
                int r = wm + mi*16 + gid;
                af[mi][0] = As[r  ][ks+tig];
                af[mi][1] = As[r+8][ks+tig];
                af[mi][2] = As[r  ][ks+tig+4];
                af[mi][3] = As[r+8][ks+tig+4];
            }
            #pragma unroll
            for (int ni = 0; ni < 4; ++ni) {
                int cn = wn + ni*8 + gid;
                uint32_t b0 = Bs[ks+tig  ][cn];
                uint32_t b1 = Bs[ks+tig+4][cn];
                #pragma unroll
                for (int mi = 0; mi < 4; ++mi)
                    mma_tf32(acc[mi][ni], af[mi], b0, b1);
            }
        }
        __syncthreads();
    }
    #pragma unroll
    for (int mi = 0; mi < 4; ++mi) {
        int r0 = by*BM + wm + mi*16 + gid;
        #pragma unroll
        for (int ni = 0; ni < 4; ++ni) {
            int cc = bx*BN + wn + ni*8 + tig*2;
            *(float2*)(C + (long)r0*N + cc)     = make_float2(acc[mi][ni][0], acc[mi][ni][1]);
            *(float2*)(C + (long)(r0+8)*N + cc) = make_float2(acc[mi][ni][2], acc[mi][ni][3]);
        }
    }
}

// ============ fused flash attention, 64-row tile, 2 CTAs/SM, wide chunks =====
// Change vs R12: K loaded in two 64-wide chunks (Ks[128][68]) and V in two
// 64-row chunks (Vs[64][132]) -> 10 syncs per j-iteration instead of 18.
// smem layout (bytes):
//   Qs  [64][132] u32 tf32    @ 0       (33792)
//   SP  [64][132] f32 / u32   @ 33792   (33792)   S then P in-place
//   KV  union                 @ 67584   (34816)   K chunk [128][68] / V chunk [64][132]
//   mrow[64] f32              @ 102400
//   lrow[64] f32              @ 102656
//   srow[64] f32              @ 102912
#define FL_SMEM 103168
__global__ void __launch_bounds__(256, 2)
flash_kernel(const float* __restrict__ Q, const float* __restrict__ Kg,
             const float* __restrict__ Vg, float* __restrict__ att) {
    extern __shared__ char smem[];
    uint32_t (*Qs)[132] = (uint32_t(*)[132])(smem);
    float    (*Sf)[132] = (float(*)[132])(smem + 33792);
    uint32_t (*Pu)[132] = (uint32_t(*)[132])(smem + 33792);
    uint32_t (*Ks)[68]  = (uint32_t(*)[68]) (smem + 67584);
    uint32_t (*Vs)[132] = (uint32_t(*)[132])(smem + 67584);
    float* mrow = (float*)(smem + 102400);
    float* lrow = (float*)(smem + 102656);
    float* srow = (float*)(smem + 102912);

    int ib = 31 - blockIdx.x;          // 64-row query block, big first
    int bh = blockIdx.y;
    int tid = threadIdx.x;
    int lane = tid & 31, warp = tid >> 5;
    int gid = lane >> 2, tig = lane & 3;
    int wm = (warp & 1) * 32, wn = (warp >> 1) * 32;   // 2x4 warp grid

    const float* Qg = Q  + (long)bh*SEQ*DH + (long)ib*64*DH;
    const float* Kb = Kg + (long)bh*SEQ*DH;
    const float* Vb = Vg + (long)bh*SEQ*DH;

    // load Q tile 64x128 (tf32)
    #pragma unroll
    for (int p = 0; p < 8; ++p) {
        int idx = tid + p*256;
        int m = idx >> 5, kq = idx & 31;
        float4 va = *(const float4*)(Qg + (long)m*DH + kq*4);
        Qs[m][kq*4+0] = f2tf(va.x); Qs[m][kq*4+1] = f2tf(va.y);
        Qs[m][kq*4+2] = f2tf(va.z); Qs[m][kq*4+3] = f2tf(va.w);
    }
    if (tid < 64) { mrow[tid] = -1e30f; lrow[tid] = 0.f; }
    __syncthreads();

    float accO[2][4][4] = {};
    int jmax = ib >> 1;

    for (int jb = 0; jb <= jmax; ++jb) {
        // ---- phase 1: S = Q @ Kj^T, two 64-wide K chunks ----
        float acc[2][4][4] = {};
        const float* Kj = Kb + (long)jb*128*DH;
        #pragma unroll
        for (int c = 0; c < 2; ++c) {
            int kbase = c*64;
            // load K chunk: 128 rows x 64 k-values (8 float4 per thread)
            #pragma unroll
            for (int p = 0; p < 8; ++p) {
                int idx = tid + p*256;
                int n = idx >> 4, colq = idx & 15;
                float4 vb = *(const float4*)(Kj + (long)n*DH + kbase + colq*4);
                Ks[n][colq*4+0] = f2tf(vb.x); Ks[n][colq*4+1] = f2tf(vb.y);
                Ks[n][colq*4+2] = f2tf(vb.z); Ks[n][colq*4+3] = f2tf(vb.w);
            }
            __syncthreads();
            #pragma unroll
            for (int ks = 0; ks < 64; ks += 8) {
                int kg = kbase + ks;
                uint32_t af[2][4];
                #pragma unroll
                for (int mi = 0; mi < 2; ++mi) {
                    int r = wm + mi*16 + gid;
                    af[mi][0] = Qs[r  ][kg+tig];
                    af[mi][1] = Qs[r+8][kg+tig];
                    af[mi][2] = Qs[r  ][kg+tig+4];
                    af[mi][3] = Qs[r+8][kg+tig+4];
                }
                #pragma unroll
                for (int ni = 0; ni < 4; ++ni) {
                    int cn = wn + ni*8 + gid;
                    uint32_t b0 = Ks[cn][ks+tig];
                    uint32_t b1 = Ks[cn][ks+tig+4];
                    #pragma unroll
                    for (int mi = 0; mi < 2; ++mi)
                        mma_tf32(acc[mi][ni], af[mi], b0, b1);
                }
            }
            __syncthreads();
        }
        // ---- phase 2: write S to smem, causal mask on last block ----
        bool diag = (jb == jmax);
        #pragma unroll
        for (int mi = 0; mi < 2; ++mi) {
            int r0 = wm + mi*16 + gid;
            int gr0 = ib*64 + r0, gr1 = gr0 + 8;
            #pragma unroll
            for (int ni = 0; ni < 4; ++ni) {
                int cc = wn + ni*8 + tig*2;
                int jc = jb*128 + cc;
                float s00 = acc[mi][ni][0], s01 = acc[mi][ni][1];
                float s10 = acc[mi][ni][2], s11 = acc[mi][ni][3];
                if (diag) {
                    if (jc   > gr0) s00 = -1e30f;
                    if (jc+1 > gr0) s01 = -1e30f;
                    if (jc   > gr1) s10 = -1e30f;
                    if (jc+1 > gr1) s11 = -1e30f;
                }
                Sf[r0  ][cc] = s00; Sf[r0  ][cc+1] = s01;
                Sf[r0+8][cc] = s10; Sf[r0+8][cc+1] = s11;
            }
        }
        __syncthreads();
        // ---- phase 3: online softmax (4 threads per row) ----
        {
            int row = tid >> 2, quad = tid & 3;
            int c0 = quad*32;
            float bm = -1e30f;
            #pragma unroll
            for (int c = 0; c < 32; ++c) bm = fmaxf(bm, Sf[row][c0+c]);
            bm = fmaxf(bm, __shfl_xor_sync(0xffffffffu, bm, 1));
            bm = fmaxf(bm, __shfl_xor_sync(0xffffffffu, bm, 2));
            float mold = mrow[row];
            float mnew = fmaxf(mold, bm);
            float f = __expf(mold - mnew);
            float sum = 0.f;
            #pragma unroll
            for (int c = 0; c < 32; ++c) {
                float p = __expf(Sf[row][c0+c] - mnew);
                sum += p;
                Pu[row][c0+c] = f2tf(p);
            }
            sum += __shfl_xor_sync(0xffffffffu, sum, 1);
            sum += __shfl_xor_sync(0xffffffffu, sum, 2);
            if (quad == 0) {
                lrow[row] = lrow[row]*f + sum;
                mrow[row] = mnew;
                srow[row] = f;
            }
        }
        __syncthreads();
        // ---- phase 4: rescale O accumulators ----
        #pragma unroll
        for (int mi = 0; mi < 2; ++mi) {
            int r0 = wm + mi*16 + gid;
            float s0 = srow[r0], s1 = srow[r0+8];
            #pragma unroll
            for (int ni = 0; ni < 4; ++ni) {
                accO[mi][ni][0] *= s0; accO[mi][ni][1] *= s0;
                accO[mi][ni][2] *= s1; accO[mi][ni][3] *= s1;
            }
        }
        // ---- phase 5: O += P @ Vj, two 64-row V chunks ----
        const float* Vj = Vb + (long)jb*128*DH;
        #pragma unroll
        for (int c = 0; c < 2; ++c) {
            int kbase = c*64;
            __syncthreads();   // Vs free (prev chunk mma done / Ks readers done)
            #pragma unroll
            for (int p = 0; p < 8; ++p) {
                int idx = tid + p*256;
                int kk = idx >> 5, nq = idx & 31;
                float4 vb = *(const float4*)(Vj + (long)(kbase+kk)*DH + nq*4);
                Vs[kk][nq*4+0] = f2tf(vb.x); Vs[kk][nq*4+1] = f2tf(vb.y);
                Vs[kk][nq*4+2] = f2tf(vb.z); Vs[kk][nq*4+3] = f2tf(vb.w);
            }
            __syncthreads();
            #pragma unroll
            for (int ks = 0; ks < 64; ks += 8) {
                int kg = kbase + ks;
                uint32_t af[2][4];
                #pragma unroll
                for (int mi = 0; mi < 2; ++mi) {
                    int r = wm + mi*16 + gid;
                    af[mi][0] = Pu[r  ][kg+tig];
                    af[mi][1] = Pu[r+8][kg+tig];
                    af[mi][2] = Pu[r  ][kg+tig+4];
                    af[mi][3] = Pu[r+8][kg+tig+4];
                }
                #pragma unroll
                for (int ni = 0; ni < 4; ++ni) {
                    int cn = wn + ni*8 + gid;
                    uint32_t b0 = Vs[ks+tig  ][cn];
                    uint32_t b1 = Vs[ks+tig+4][cn];
                    #pragma unroll
                    for (int mi = 0; mi < 2; ++mi)
                        mma_tf32(accO[mi][ni], af[mi], b0, b1);
                }
            }
        }
        __syncthreads();   // SP / KV free for next iteration
    }

    // ---- epilogue: divide by l, write att ----
    float* Og = att + (long)bh*SEQ*DH + (long)ib*64*DH;
    #pragma unroll
    for (int mi = 0; mi < 2; ++mi) {
        int r0 = wm + mi*16 + gid;
        float inv0 = 1.f / lrow[r0];
        float inv1 = 1.f / lrow[r0+8];
        #pragma unroll
        for (int ni = 0; ni < 4; ++ni) {
            int cc = wn + ni*8 + tig*2;
            *(float2*)(Og + (long)r0*DH + cc) =
                make_float2(accO[mi][ni][0]*inv0, accO[mi][ni][1]*inv0);
            *(float2*)(Og + (long)(r0+8)*DH + cc) =
                make_float2(accO[mi][ni][2]*inv1, accO[mi][ni][3]*inv1);
        }
    }
}

// ---------------- L2 norm * sqrt(DIM) * gamma ----------------
__global__ void norm_kernel(const float* __restrict__ x,
                            const float* __restrict__ gamma,
                            float* __restrict__ xn) {
    int row = blockIdx.x;
    const float* xr = x + (long)row*DIM;
    __shared__ float red[256];
    float s = 0.f;
    for (int j = threadIdx.x; j < DIM; j += 256) { float v = xr[j]; s += v*v; }
    red[threadIdx.x] = s; __syncthreads();
    for (int st = 128; st > 0; st >>= 1) {
        if (threadIdx.x < st) red[threadIdx.x] += red[threadIdx.x+st];
        __syncthreads();
    }
    float nrm = fmaxf(sqrtf(red[0]), 1e-12f);
    float scale = 32.0f / nrm;
    for (int j = threadIdx.x; j < DIM; j += 256)
        xn[(long)row*DIM + j] = xr[j] * scale * gamma[j];
}

// ---------------- RoPE freq table ----------------
__global__ void freq_kernel(float* __restrict__ f) {
    int i = threadIdx.x;
    if (i < 64) f[i] = (float)exp(-(double)i * 0.14391156831212787);
}

// ---------------- RoPE / scale / elu transform ----------------
__global__ void transform_kernel(const float* __restrict__ qkv,
                                 const float* __restrict__ freq,
                                 float* __restrict__ qo, float* __restrict__ ko,
                                 float* __restrict__ vo, float* __restrict__ qe,
                                 float* __restrict__ ke) {
    int bn = blockIdx.x;
    int b = bn >> 11, n = bn & 2047;
    const float* base = qkv + (long)bn*QKVC;
    const float sc = 0.08838834764831845f;
    __shared__ float fs[64];
    if (threadIdx.x < 64) fs[threadIdx.x] = freq[threadIdx.x];
    __syncthreads();

    for (int p = threadIdx.x; p < HEADS*64; p += blockDim.x) {
        int h = p >> 6, i = p & 63;
        float ang = (float)n * fs[i];
        float s, c;
        sincosf(ang, &s, &c);
        long oidx = ((long)(b*HEADS+h)*SEQ + n)*DH + 2*i;
        float q0 = base[h*DH + 2*i]   * sc;
        float q1 = base[h*DH + 2*i+1] * sc;
        float r0 = q0*c - q1*s, r1 = q1*c + q0*s;
        qo[oidx] = r0; qo[oidx+1] = r1;
        qe[oidx]   = (r0 > 0.f) ? r0 + 1.f : __expf(r0);
        qe[oidx+1] = (r1 > 0.f) ? r1 + 1.f : __expf(r1);
        float k0 = base[DIM + h*DH + 2*i];
        float k1 = base[DIM + h*DH + 2*i+1];
        float s0 = k0*c - k1*s, s1 = k1*c + k0*s;
        ko[oidx] = s0; ko[oidx+1] = s1;
        ke[oidx]   = (s0 > 0.f) ? s0 + 1.f : __expf(s0);
        ke[oidx+1] = (s1 > 0.f) ? s1 + 1.f : __expf(s1);
    }
    for (int d = threadIdx.x; d < DIM; d += blockDim.x) {
        int h = d >> 7, dd = d & 127;
        vo[((long)(b*HEADS+h)*SEQ + n)*DH + dd] = base[2*DIM + d];
    }
}

// ---------------- blend ----------------
__global__ void blend_kernel(const float* __restrict__ qe,
                             const float* __restrict__ att,
                             const float* __restrict__ mo,
                             const float* __restrict__ pnorm,
                             const float* __restrict__ head_gates,
                             float* __restrict__ comb) {
    int gw = (blockIdx.x*blockDim.x + threadIdx.x) >> 5;
    int lane = threadIdx.x & 31;
    if (gw >= BH*SEQ) return;
    int bh = gw >> 11, n = gw & 2047;
    int b = bh >> 3, h = bh & 7;
    long ro = ((long)bh*SEQ + n)*DH;
    const float* qr = qe + ro;
    const float* pn = pnorm + bh*DH;
    float dot = 0.f;
    #pragma unroll
    for (int r = 0; r < 4; ++r) { int d = lane + r*32; dot += qr[d]*pn[d]; }
    #pragma unroll
    for (int o = 16; o; o >>= 1) dot += __shfl_xor_sync(0xffffffffu, dot, o);
    float inv = 1.f / fmaxf(dot, 1e-10f);
    float g = 1.f / (1.f + __expf(-head_gates[h]));
    const float* ar = att + ro;
    const float* mr = mo + ro;
    float* cr = comb + ((long)(b*SEQ + n))*DIM + h*DH;
    #pragma unroll
    for (int r = 0; r < 4; ++r) {
        int d = lane + r*32;
        cr[d] = ar[d]*g + mr[d]*inv*(1.f - g);
    }
}

// ---------------- vprime ----------------
__global__ void vprime_kernel(const float* __restrict__ ke,
                              const float* __restrict__ v,
                              const float* __restrict__ dv,
                              const float* __restrict__ pnorm,
                              float* __restrict__ vp) {
    int gw = (blockIdx.x*blockDim.x + threadIdx.x) >> 5;
    int lane = threadIdx.x & 31;
    if (gw >= BH*SEQ) return;
    int bh = gw >> 11;
    long ro = (long)gw*DH;
    const float* kr = ke + ro;
    const float* pn = pnorm + bh*DH;
    float dot = 0.f;
    #pragma unroll
    for (int r = 0; r < 4; ++r) { int d = lane + r*32; dot += kr[d]*pn[d]; }
    #pragma unroll
    for (int o = 16; o; o >>= 1) dot += __shfl_xor_sync(0xffffffffu, dot, o);
    float inv = 1.f / fmaxf(dot, 1e-10f);
    #pragma unroll
    for (int r = 0; r < 4; ++r) {
        int d = lane + r*32;
        vp[ro + d] = v[ro + d] - dv[ro + d]*inv;
    }
}

// ---------------- new_kv split-K fp32 ----------------
__global__ void __launch_bounds__(256)
nkv_partial(const float* __restrict__ ke, const float* __restrict__ vp,
            float* __restrict__ part) {
    int split = blockIdx.x, bh = blockIdx.y;
    __shared__ float Ks[32][128];
    __shared__ float Vs[32][128];
    int tid = threadIdx.x;
    int tx = tid & 15, ty = tid >> 4;
    float acc[8][8] = {};
    long base = ((long)bh*SEQ + split*128)*DH;
    for (int c = 0; c < 4; ++c) {
        for (int idx = tid; idx < 32*128; idx += 256) {
            int r = idx >> 7, col = idx & 127;
            long off = base + (long)(c*32 + r)*DH + col;
            Ks[r][col] = ke[off];
            Vs[r][col] = vp[off];
        }
        __syncthreads();
        #pragma unroll
        for (int nn = 0; nn < 32; ++nn) {
            float a[8], b[8];
            #pragma unroll
            for (int u = 0; u < 8; ++u) a[u] = Ks[nn][ty*8+u];
            #pragma unroll
            for (int v = 0; v < 8; ++v) b[v] = Vs[nn][tx*8+v];
            #pragma unroll
            for (int u = 0; u < 8; ++u)
                #pragma unroll
                for (int v = 0; v < 8; ++v) acc[u][v] += a[u]*b[v];
        }
        __syncthreads();
    }
    float* pg = part + ((long)(split*BH + bh))*DH*DH;
    #pragma unroll
    for (int u = 0; u < 8; ++u)
        #pragma unroll
        for (int v = 0; v < 8; ++v)
            pg[(ty*8+u)*DH + tx*8+v] = acc[u][v];
}

__global__ void nkv_reduce(const float* __restrict__ part,
                           const float* __restrict__ pkv,
                           float* __restrict__ out) {
    int bh = blockIdx.y;
    int e = blockIdx.x*256 + threadIdx.x;
    float s = pkv[(long)bh*DH*DH + e];
    #pragma unroll
    for (int sp = 0; sp < 16; ++sp)
        s += part[((long)(sp*BH + bh))*DH*DH + e];
    out[(long)bh*DH*DH + e] = s;
}

// ---------------- new_norm ----------------
__global__ void nnorm_partial(const float* __restrict__ ke, float* __restrict__ part) {
    int chunk = blockIdx.x, bh = blockIdx.y, k = threadIdx.x;
    float s = 0.f;
    long base = ((long)bh*SEQ + chunk*128)*DH;
    for (int n = 0; n < 128; ++n) s += ke[base + (long)n*DH + k];
    part[(bh*16 + chunk)*DH + k] = s;
}
__global__ void nnorm_reduce(const float* __restrict__ part,
                             const float* __restrict__ pnorm,
                             float* __restrict__ out) {
    int bh = blockIdx.x, k = threadIdx.x;
    float s = pnorm[bh*DH + k];
    #pragma unroll
    for (int c = 0; c < 16; ++c) s += part[(bh*16 + c)*DH + k];
    out[bh*DH + k] = s;
}

// ---------------- launch ----------------
extern "C" void kernel_launch(void* const* d_in, const int* in_sizes, int n_in,
                              void* d_out, int out_size) {
    const float* x          = (const float*)d_in[0];
    const float* gamma      = (const float*)d_in[1];
    const float* w_qkv      = (const float*)d_in[2];
    const float* w_out      = (const float*)d_in[3];
    const float* head_gates = (const float*)d_in[4];
    const float* past_kv    = (const float*)d_in[5];
    const float* past_norm  = (const float*)d_in[6];
    float* out = (float*)d_out;

    float *xn, *qkv, *q, *k, *v, *qe, *ke, *vp, *att, *mo, *dv, *comb, *nkvp, *nnp, *freq;
    cudaGetSymbolAddress((void**)&xn,   g_xn);
    cudaGetSymbolAddress((void**)&qkv,  g_qkv);
    cudaGetSymbolAddress((void**)&q,    g_q);
    cudaGetSymbolAddress((void**)&k,    g_k);
    cudaGetSymbolAddress((void**)&v,    g_v);
    cudaGetSymbolAddress((void**)&qe,   g_qe);
    cudaGetSymbolAddress((void**)&ke,   g_ke);
    cudaGetSymbolAddress((void**)&vp,   g_vp);
    cudaGetSymbolAddress((void**)&att,  g_att);
    cudaGetSymbolAddress((void**)&mo,   g_mo);
    cudaGetSymbolAddress((void**)&dv,   g_dv);
    cudaGetSymbolAddress((void**)&comb, g_comb);
    cudaGetSymbolAddress((void**)&nkvp, g_nkv_part);
    cudaGetSymbolAddress((void**)&nnp,  g_nn_part);
    cudaGetSymbolAddress((void**)&freq, g_freq);

    // idempotent, deterministic; safe on every call
    cudaFuncSetAttribute(flash_kernel,
                         cudaFuncAttributeMaxDynamicSharedMemorySize, FL_SMEM);

    // 1. L2 normalize + gamma scale; RoPE freq table
    norm_kernel<<<ROWS, 256>>>(x, gamma, xn);
    freq_kernel<<<1, 64>>>(freq);

    // 2. qkv = xn @ w_qkv (tf32)
    tfgemm_nn<<<dim3(QKVC/128, ROWS/128, 1), 256>>>(xn, w_qkv, qkv,
        QKVC, DIM, 0, 0, 0);

    // 3. split/scale/RoPE/elu
    transform_kernel<<<ROWS, 256>>>(qkv, freq, q, k, v, qe, ke);

    // 4-6. fused flash attention (64-row tiles, 2 CTAs/SM, wide K/V chunks)
    flash_kernel<<<dim3(32, BH), 256, FL_SMEM>>>(q, k, v, att);

    // 7. mem_out = qe @ past_kv per (b,h)
    tfgemm_nn<<<dim3(1, SEQ/128, BH), 256>>>(qe, past_kv, mo,
        DH, DH, (long)SEQ*DH, (long)DH*DH, (long)SEQ*DH);

    // 8. delta_v = ke @ past_kv per (b,h)
    tfgemm_nn<<<dim3(1, SEQ/128, BH), 256>>>(ke, past_kv, dv,
        DH, DH, (long)SEQ*DH, (long)DH*DH, (long)SEQ*DH);

    // 9. blend att + memory path -> comb
    blend_kernel<<<(BH*SEQ*32 + 255)/256, 256>>>(qe, att, mo, past_norm, head_gates, comb);

    // 10. vprime = v - delta_v / clip(ke . past_norm)
    vprime_kernel<<<(BH*SEQ*32 + 255)/256, 256>>>(ke, v, dv, past_norm, vp);

    // 11. new_kv = ke^T @ vprime + past_kv (fp32 split-K, deterministic)
    nkv_partial<<<dim3(16, BH), 256>>>(ke, vp, nkvp);
    nkv_reduce<<<dim3(DH*DH/256, BH), 256>>>(nkvp, past_kv, out + NKV_OFF);

    // 12. new_norm = sum_n ke + past_norm
    nnorm_partial<<<dim3(16, BH), 128>>>(ke, nnp);
    nnorm_reduce<<<BH, 128>>>(nnp, past_norm, out + NNORM_OFF);

    // 13. final projection (tf32): out = comb @ w_out
    tfgemm_nn<<<dim3(DIM/128, ROWS/128, 1), 256>>>(comb, w_out, out + OUT_OFF,
        DIM, DIM, 0, 0, 0);
}

// round 14
// speedup vs baseline: 1.0226x; 1.0226x over previous
#include <cuda_runtime.h>
#include <cstdint>
#include <math.h>

// Problem dims
#define BATCH 2
#define SEQ   2048
#define DIM   1024
#define HEADS 8
#define DH    128
#define BH    (BATCH*HEADS)          // 16
#define ROWS  (BATCH*SEQ)            // 4096
#define QKVC  (3*HEADS*DH)           // 3072

// Output packing offsets (out, new_kv, new_norm concatenated)
#define OUT_OFF  0L
#define NKV_OFF  ((long)ROWS*DIM)
#define NNORM_OFF (NKV_OFF + (long)BH*DH*DH)

// ---------------- device scratch (allocation-free) ----------------
__device__ float g_xn[ROWS*DIM];
__device__ float g_qkv[(long)ROWS*QKVC];
__device__ float g_q [BH*SEQ*DH];
__device__ float g_k [BH*SEQ*DH];
__device__ float g_v [BH*SEQ*DH];
__device__ float g_qe[BH*SEQ*DH];
__device__ float g_ke[BH*SEQ*DH];
__device__ float g_vp[BH*SEQ*DH];
__device__ float g_att[BH*SEQ*DH];
__device__ float g_mo[BH*SEQ*DH];
__device__ float g_dv[BH*SEQ*DH];
__device__ float g_comb[ROWS*DIM];
__device__ float g_nkv_part[16*BH*DH*DH];
__device__ float g_nn_part[BH*16*DH];
__device__ float g_freq[64];

// ---------------- tf32 helpers ----------------
__device__ __forceinline__ uint32_t f2tf(float x) {
    uint32_t r;
    asm("cvt.rna.tf32.f32 %0, %1;" : "=r"(r) : "f"(x));
    return r;
}
__device__ __forceinline__ void mma_tf32(float* c, const uint32_t* a,
                                         uint32_t b0, uint32_t b1) {
    asm volatile(
        "mma.sync.aligned.m16n8k8.row.col.f32.tf32.tf32.f32 "
        "{%0,%1,%2,%3}, {%4,%5,%6,%7}, {%8,%9}, {%0,%1,%2,%3};"
        : "+f"(c[0]), "+f"(c[1]), "+f"(c[2]), "+f"(c[3])
        : "r"(a[0]), "r"(a[1]), "r"(a[2]), "r"(a[3]), "r"(b0), "r"(b1));
}

#define BM 128
#define BN 128
#define BKT 32
#define BKP 36      // padded k-stride for [rows][k] layouts
#define BNP 132     // padded n-stride for [k][n] layout

// ============ tf32 GEMM NN: C[M,N] = A[M,K] @ B[K,N], row-major ============
__global__ void __launch_bounds__(256)
tfgemm_nn(const float* __restrict__ A, const float* __restrict__ B,
          float* __restrict__ C, int N, int K,
          long sA, long sB, long sC) {
    A += (long)blockIdx.z * sA;
    B += (long)blockIdx.z * sB;
    C += (long)blockIdx.z * sC;
    int by = blockIdx.y, bx = blockIdx.x;

    __shared__ uint32_t As[BM][BKP];
    __shared__ uint32_t Bs[BKT][BNP];

    int tid = threadIdx.x;
    int lane = tid & 31, warp = tid >> 5;
    int gid = lane >> 2, tig = lane & 3;
    int wm = (warp & 1) * 64, wn = (warp >> 1) * 32;

    float acc[4][4][4] = {};
    const float* Ag = A + (long)by*BM*K;
    const float* Bg = B + bx*BN;

    for (int k0 = 0; k0 < K; k0 += BKT) {
        #pragma unroll
        for (int p = 0; p < 4; ++p) {
            int idx = tid + p*256;
            int m = idx >> 3, kq = idx & 7;
            float4 va = *(const float4*)(Ag + (long)m*K + k0 + kq*4);
            As[m][kq*4+0] = f2tf(va.x); As[m][kq*4+1] = f2tf(va.y);
            As[m][kq*4+2] = f2tf(va.z); As[m][kq*4+3] = f2tf(va.w);
        }
        #pragma unroll
        for (int p = 0; p < 4; ++p) {
            int idx = tid + p*256;
            int kk = idx >> 5, nq = idx & 31;
            float4 vb = *(const float4*)(Bg + (long)(k0+kk)*N + nq*4);
            Bs[kk][nq*4+0] = f2tf(vb.x); Bs[kk][nq*4+1] = f2tf(vb.y);
            Bs[kk][nq*4+2] = f2tf(vb.z); Bs[kk][nq*4+3] = f2tf(vb.w);
        }
        __syncthreads();
        #pragma unroll
        for (int ks = 0; ks < BKT; ks += 8) {
            uint32_t af[4][4];
            #pragma unroll
            for (int mi = 0; mi < 4; ++mi) {
                int r = wm + mi*16 + gid;
                af[mi][0] = As[r  ][ks+tig];
                af[mi][1] = As[r+8][ks+tig];
                af[mi][2] = As[r  ][ks+tig+4];
                af[mi][3] = As[r+8][ks+tig+4];
            }
            #pragma unroll
            for (int ni = 0; ni < 4; ++ni) {
                int cn = wn + ni*8 + gid;
                uint32_t b0 = Bs[ks+tig  ][cn];
                uint32_t b1 = Bs[ks+tig+4][cn];
                #pragma unroll
                for (int mi = 0; mi < 4; ++mi)
                    mma_tf32(acc[mi][ni], af[mi], b0, b1);
            }
        }
        __syncthreads();
    }
    #pragma unroll
    for (int mi = 0; mi < 4; ++mi) {
        int r0 = by*BM + wm + mi*16 + gid;
        #pragma unroll
        for (int ni = 0; ni < 4; ++ni) {
            int cc = bx*BN + wn + ni*8 + tig*2;
            *(float2*)(C + (long)r0*N + cc)     = make_float2(acc[mi][ni][0], acc[mi][ni][1]);
            *(float2*)(C + (long)(r0+8)*N + cc) = make_float2(acc[mi][ni][2], acc[mi][ni][3]);
        }
    }
}

// ============ fused mem_out + delta_v GEMM ============
// grid (1, SEQ/128, BH*2); z = bh*2 + which (0: qe->mo, 1: ke->dv)
__global__ void __launch_bounds__(256)
memdv_kernel(const float* __restrict__ qe, const float* __restrict__ ke,
             const float* __restrict__ pkv,
             float* __restrict__ mo, float* __restrict__ dv) {
    int z = blockIdx.z;
    int bh = z >> 1, which = z & 1;
    const float* A = (which ? ke : qe) + (long)bh*SEQ*DH + (long)blockIdx.y*BM*DH;
    const float* B = pkv + (long)bh*DH*DH;
    float* C = (which ? dv : mo) + (long)bh*SEQ*DH + (long)blockIdx.y*BM*DH;

    __shared__ uint32_t As[BM][BKP];
    __shared__ uint32_t Bs[BKT][BNP];

    int tid = threadIdx.x;
    int lane = tid & 31, warp = tid >> 5;
    int gid = lane >> 2, tig = lane & 3;
    int wm = (warp & 1) * 64, wn = (warp >> 1) * 32;

    float acc[4][4][4] = {};

    for (int k0 = 0; k0 < DH; k0 += BKT) {
        #pragma unroll
        for (int p = 0; p < 4; ++p) {
            int idx = tid + p*256;
            int m = idx >> 3, kq = idx & 7;
            float4 va = *(const float4*)(A + (long)m*DH + k0 + kq*4);
            As[m][kq*4+0] = f2tf(va.x); As[m][kq*4+1] = f2tf(va.y);
            As[m][kq*4+2] = f2tf(va.z); As[m][kq*4+3] = f2tf(va.w);
        }
        #pragma unroll
        for (int p = 0; p < 4; ++p) {
            int idx = tid + p*256;
            int kk = idx >> 5, nq = idx & 31;
            float4 vb = *(const float4*)(B + (long)(k0+kk)*DH + nq*4);
            Bs[kk][nq*4+0] = f2tf(vb.x); Bs[kk][nq*4+1] = f2tf(vb.y);
            Bs[kk][nq*4+2] = f2tf(vb.z); Bs[kk][nq*4+3] = f2tf(vb.w);
        }
        __syncthreads();
        #pragma unroll
        for (int ks = 0; ks < BKT; ks += 8) {
            uint32_t af[4][4];
            #pragma unroll
            for (int mi = 0; mi < 4; ++mi) {
                int r = wm + mi*16 + gid;
                af[mi][0] = As[r  ][ks+tig];
                af[mi][1] = As[r+8][ks+tig];
                af[mi][2] = As[r  ][ks+tig+4];
                af[mi][3] = As[r+8][ks+tig+4];
            }
            #pragma unroll
            for (int ni = 0; ni < 4; ++ni) {
                int cn = wn + ni*8 + gid;
                uint32_t b0 = Bs[ks+tig  ][cn];
                uint32_t b1 = Bs[ks+tig+4][cn];
                #pragma unroll
                for (int mi = 0; mi < 4; ++mi)
                    mma_tf32(acc[mi][ni], af[mi], b0, b1);
            }
        }
        __syncthreads();
    }
    #pragma unroll
    for (int mi = 0; mi < 4; ++mi) {
        int r0 = wm + mi*16 + gid;
        #pragma unroll
        for (int ni = 0; ni < 4; ++ni) {
            int cc = wn + ni*8 + tig*2;
            *(float2*)(C + (long)r0*DH + cc)     = make_float2(acc[mi][ni][0], acc[mi][ni][1]);
            *(float2*)(C + (long)(r0+8)*DH + cc) = make_float2(acc[mi][ni][2], acc[mi][ni][3]);
        }
    }
}

// ============ fused flash attention (R12 config: narrow chunks, 2 CTAs/SM) ===
// smem layout (bytes):
//   Qs  [64][132] u32 tf32    @ 0       (33792)
//   SP  [64][132] f32 / u32   @ 33792   (33792)   S then P in-place
//   KV  union                 @ 67584   (18432)   K chunk [128][36] / V chunk [32][132]
//   mrow[64] f32              @ 86016
//   lrow[64] f32              @ 86272
//   srow[64] f32              @ 86528
#define FL_SMEM 86784
__global__ void __launch_bounds__(256, 2)
flash_kernel(const float* __restrict__ Q, const float* __restrict__ Kg,
             const float* __restrict__ Vg, float* __restrict__ att) {
    extern __shared__ char smem[];
    uint32_t (*Qs)[132] = (uint32_t(*)[132])(smem);
    float    (*Sf)[132] = (float(*)[132])(smem + 33792);
    uint32_t (*Pu)[132] = (uint32_t(*)[132])(smem + 33792);
    uint32_t (*Ks)[36]  = (uint32_t(*)[36]) (smem + 67584);
    uint32_t (*Vs)[132] = (uint32_t(*)[132])(smem + 67584);
    float* mrow = (float*)(smem + 86016);
    float* lrow = (float*)(smem + 86272);
    float* srow = (float*)(smem + 86528);

    int ib = 31 - blockIdx.x;          // 64-row query block, big first
    int bh = blockIdx.y;
    int tid = threadIdx.x;
    int lane = tid & 31, warp = tid >> 5;
    int gid = lane >> 2, tig = lane & 3;
    int wm = (warp & 1) * 32, wn = (warp >> 1) * 32;   // 2x4 warp grid

    const float* Qg = Q  + (long)bh*SEQ*DH + (long)ib*64*DH;
    const float* Kb = Kg + (long)bh*SEQ*DH;
    const float* Vb = Vg + (long)bh*SEQ*DH;

    #pragma unroll
    for (int p = 0; p < 8; ++p) {
        int idx = tid + p*256;
        int m = idx >> 5, kq = idx & 31;
        float4 va = *(const float4*)(Qg + (long)m*DH + kq*4);
        Qs[m][kq*4+0] = f2tf(va.x); Qs[m][kq*4+1] = f2tf(va.y);
        Qs[m][kq*4+2] = f2tf(va.z); Qs[m][kq*4+3] = f2tf(va.w);
    }
    if (tid < 64) { mrow[tid] = -1e30f; lrow[tid] = 0.f; }
    __syncthreads();

    float accO[2][4][4] = {};
    int jmax = ib >> 1;

    for (int jb = 0; jb <= jmax; ++jb) {
        float acc[2][4][4] = {};
        const float* Kj = Kb + (long)jb*128*DH;
        for (int k0 = 0; k0 < DH; k0 += BKT) {
            #pragma unroll
            for (int p = 0; p < 4; ++p) {
                int idx = tid + p*256;
                int n = idx >> 3, kq = idx & 7;
                float4 vb = *(const float4*)(Kj + (long)n*DH + k0 + kq*4);
                Ks[n][kq*4+0] = f2tf(vb.x); Ks[n][kq*4+1] = f2tf(vb.y);
                Ks[n][kq*4+2] = f2tf(vb.z); Ks[n][kq*4+3] = f2tf(vb.w);
            }
            __syncthreads();
            #pragma unroll
            for (int ks = 0; ks < BKT; ks += 8) {
                int kg = k0 + ks;
                uint32_t af[2][4];
                #pragma unroll
                for (int mi = 0; mi < 2; ++mi) {
                    int r = wm + mi*16 + gid;
                    af[mi][0] = Qs[r  ][kg+tig];
                    af[mi][1] = Qs[r+8][kg+tig];
                    af[mi][2] = Qs[r  ][kg+tig+4];
                    af[mi][3] = Qs[r+8][kg+tig+4];
                }
                #pragma unroll
                for (int ni = 0; ni < 4; ++ni) {
                    int cn = wn + ni*8 + gid;
                    uint32_t b0 = Ks[cn][ks+tig];
                    uint32_t b1 = Ks[cn][ks+tig+4];
                    #pragma unroll
                    for (int mi = 0; mi < 2; ++mi)
                        mma_tf32(acc[mi][ni], af[mi], b0, b1);
                }
            }
            __syncthreads();
        }
        bool diag = (jb == jmax);
        #pragma unroll
        for (int mi = 0; mi < 2; ++mi) {
            int r0 = wm + mi*16 + gid;
            int gr0 = ib*64 + r0, gr1 = gr0 + 8;
            #pragma unroll
            for (int ni = 0; ni < 4; ++ni) {
                int cc = wn + ni*8 + tig*2;
                int jc = jb*128 + cc;
                float s00 = acc[mi][ni][0], s01 = acc[mi][ni][1];
                float s10 = acc[mi][ni][2], s11 = acc[mi][ni][3];
                if (diag) {
                    if (jc   > gr0) s00 = -1e30f;
                    if (jc+1 > gr0) s01 = -1e30f;
                    if (jc   > gr1) s10 = -1e30f;
                    if (jc+1 > gr1) s11 = -1e30f;
                }
                Sf[r0  ][cc] = s00; Sf[r0  ][cc+1] = s01;
                Sf[r0+8][cc] = s10; Sf[r0+8][cc+1] = s11;
            }
        }
        __syncthreads();
        {
            int row = tid >> 2, quad = tid & 3;
            int c0 = quad*32;
            float bm = -1e30f;
            #pragma unroll
            for (int c = 0; c < 32; ++c) bm = fmaxf(bm, Sf[row][c0+c]);
            bm = fmaxf(bm, __shfl_xor_sync(0xffffffffu, bm, 1));
            bm = fmaxf(bm, __shfl_xor_sync(0xffffffffu, bm, 2));
            float mold = mrow[row];
            float mnew = fmaxf(mold, bm);
            float f = __expf(mold - mnew);
            float sum = 0.f;
            #pragma unroll
            for (int c = 0; c < 32; ++c) {
                float p = __expf(Sf[row][c0+c] - mnew);
                sum += p;
                Pu[row][c0+c] = f2tf(p);
            }
            sum += __shfl_xor_sync(0xffffffffu, sum, 1);
            sum += __shfl_xor_sync(0xffffffffu, sum, 2);
            if (quad == 0) {
                lrow[row] = lrow[row]*f + sum;
                mrow[row] = mnew;
                srow[row] = f;
            }
        }
        __syncthreads();
        #pragma unroll
        for (int mi = 0; mi < 2; ++mi) {
            int r0 = wm + mi*16 + gid;
            float s0 = srow[r0], s1 = srow[r0+8];
            #pragma unroll
            for (int ni = 0; ni < 4; ++ni) {
                accO[mi][ni][0] *= s0; accO[mi][ni][1] *= s0;
                accO[mi][ni][2] *= s1; accO[mi][ni][3] *= s1;
            }
        }
        const float* Vj = Vb + (long)jb*128*DH;
        for (int kk0 = 0; kk0 < 128; kk0 += BKT) {
            __syncthreads();
            #pragma unroll
            for (int p = 0; p < 4; ++p) {
                int idx = tid + p*256;
                int kk = idx >> 5, nq = idx & 31;
                float4 vb = *(const float4*)(Vj + (long)(kk0+kk)*DH + nq*4);
                Vs[kk][nq*4+0] = f2tf(vb.x); Vs[kk][nq*4+1] = f2tf(vb.y);
                Vs[kk][nq*4+2] = f2tf(vb.z); Vs[kk][nq*4+3] = f2tf(vb.w);
            }
            __syncthreads();
            #pragma unroll
            for (int ks = 0; ks < BKT; ks += 8) {
                int kg = kk0 + ks;
                uint32_t af[2][4];
                #pragma unroll
                for (int mi = 0; mi < 2; ++mi) {
                    int r = wm + mi*16 + gid;
                    af[mi][0] = Pu[r  ][kg+tig];
                    af[mi][1] = Pu[r+8][kg+tig];
                    af[mi][2] = Pu[r  ][kg+tig+4];
                    af[mi][3] = Pu[r+8][kg+tig+4];
                }
                #pragma unroll
                for (int ni = 0; ni < 4; ++ni) {
                    int cn = wn + ni*8 + gid;
                    uint32_t b0 = Vs[ks+tig  ][cn];
                    uint32_t b1 = Vs[ks+tig+4][cn];
                    #pragma unroll
                    for (int mi = 0; mi < 2; ++mi)
                        mma_tf32(accO[mi][ni], af[mi], b0, b1);
                }
            }
        }
        __syncthreads();
    }

    float* Og = att + (long)bh*SEQ*DH + (long)ib*64*DH;
    #pragma unroll
    for (int mi = 0; mi < 2; ++mi) {
        int r0 = wm + mi*16 + gid;
        float inv0 = 1.f / lrow[r0];
        float inv1 = 1.f / lrow[r0+8];
        #pragma unroll
        for (int ni = 0; ni < 4; ++ni) {
            int cc = wn + ni*8 + tig*2;
            *(float2*)(Og + (long)r0*DH + cc) =
                make_float2(accO[mi][ni][0]*inv0, accO[mi][ni][1]*inv0);
            *(float2*)(Og + (long)(r0+8)*DH + cc) =
                make_float2(accO[mi][ni][2]*inv1, accO[mi][ni][3]*inv1);
        }
    }
}

// ---------------- L2 norm * sqrt(DIM) * gamma ----------------
__global__ void norm_kernel(const float* __restrict__ x,
                            const float* __restrict__ gamma,
                            float* __restrict__ xn) {
    int row = blockIdx.x;
    const float* xr = x + (long)row*DIM;
    __shared__ float red[256];
    float s = 0.f;
    for (int j = threadIdx.x; j < DIM; j += 256) { float v = xr[j]; s += v*v; }
    red[threadIdx.x] = s; __syncthreads();
    for (int st = 128; st > 0; st >>= 1) {
        if (threadIdx.x < st) red[threadIdx.x] += red[threadIdx.x+st];
        __syncthreads();
    }
    float nrm = fmaxf(sqrtf(red[0]), 1e-12f);
    float scale = 32.0f / nrm;
    for (int j = threadIdx.x; j < DIM; j += 256)
        xn[(long)row*DIM + j] = xr[j] * scale * gamma[j];
}

// ---------------- RoPE freq table ----------------
__global__ void freq_kernel(float* __restrict__ f) {
    int i = threadIdx.x;
    if (i < 64) f[i] = (float)exp(-(double)i * 0.14391156831212787);
}

// ---------------- RoPE / scale / elu transform ----------------
__global__ void transform_kernel(const float* __restrict__ qkv,
                                 const float* __restrict__ freq,
                                 float* __restrict__ qo, float* __restrict__ ko,
                                 float* __restrict__ vo, float* __restrict__ qe,
                                 float* __restrict__ ke) {
    int bn = blockIdx.x;
    int b = bn >> 11, n = bn & 2047;
    const float* base = qkv + (long)bn*QKVC;
    const float sc = 0.08838834764831845f;
    __shared__ float fs[64];
    if (threadIdx.x < 64) fs[threadIdx.x] = freq[threadIdx.x];
    __syncthreads();

    for (int p = threadIdx.x; p < HEADS*64; p += blockDim.x) {
        int h = p >> 6, i = p & 63;
        float ang = (float)n * fs[i];
        float s, c;
        sincosf(ang, &s, &c);
        long oidx = ((long)(b*HEADS+h)*SEQ + n)*DH + 2*i;
        float q0 = base[h*DH + 2*i]   * sc;
        float q1 = base[h*DH + 2*i+1] * sc;
        float r0 = q0*c - q1*s, r1 = q1*c + q0*s;
        qo[oidx] = r0; qo[oidx+1] = r1;
        qe[oidx]   = (r0 > 0.f) ? r0 + 1.f : __expf(r0);
        qe[oidx+1] = (r1 > 0.f) ? r1 + 1.f : __expf(r1);
        float k0 = base[DIM + h*DH + 2*i];
        float k1 = base[DIM + h*DH + 2*i+1];
        float s0 = k0*c - k1*s, s1 = k1*c + k0*s;
        ko[oidx] = s0; ko[oidx+1] = s1;
        ke[oidx]   = (s0 > 0.f) ? s0 + 1.f : __expf(s0);
        ke[oidx+1] = (s1 > 0.f) ? s1 + 1.f : __expf(s1);
    }
    for (int d = threadIdx.x; d < DIM; d += blockDim.x) {
        int h = d >> 7, dd = d & 127;
        vo[((long)(b*HEADS+h)*SEQ + n)*DH + dd] = base[2*DIM + d];
    }
}

// ---------------- fused blend + vprime (warp per row) ----------------
__global__ void blendv_kernel(const float* __restrict__ qe,
                              const float* __restrict__ ke,
                              const float* __restrict__ att,
                              const float* __restrict__ mo,
                              const float* __restrict__ v,
                              const float* __restrict__ dv,
                              const float* __restrict__ pnorm,
                              const float* __restrict__ head_gates,
                              float* __restrict__ comb,
                              float* __restrict__ vp) {
    int gw = (blockIdx.x*blockDim.x + threadIdx.x) >> 5;
    int lane = threadIdx.x & 31;
    if (gw >= BH*SEQ) return;
    int bh = gw >> 11, n = gw & 2047;
    int b = bh >> 3, h = bh & 7;
    long ro = ((long)bh*SEQ + n)*DH;
    const float* pn = pnorm + bh*DH;

    float qdot = 0.f, kdot = 0.f;
    #pragma unroll
    for (int r = 0; r < 4; ++r) {
        int d = lane + r*32;
        float p = pn[d];
        qdot += qe[ro + d]*p;
        kdot += ke[ro + d]*p;
    }
    #pragma unroll
    for (int o = 16; o; o >>= 1) {
        qdot += __shfl_xor_sync(0xffffffffu, qdot, o);
        kdot += __shfl_xor_sync(0xffffffffu, kdot, o);
    }
    float qinv = 1.f / fmaxf(qdot, 1e-10f);
    float kinv = 1.f / fmaxf(kdot, 1e-10f);
    float g = 1.f / (1.f + __expf(-head_gates[h]));

    float* cr = comb + ((long)(b*SEQ + n))*DIM + h*DH;
    #pragma unroll
    for (int r = 0; r < 4; ++r) {
        int d = lane + r*32;
        cr[d] = att[ro + d]*g + mo[ro + d]*qinv*(1.f - g);
        vp[ro + d] = v[ro + d] - dv[ro + d]*kinv;
    }
}

// ---------------- new_kv split-K fp32 (+ fused new_norm partials) ----------
__global__ void __launch_bounds__(256)
nkv_partial(const float* __restrict__ ke, const float* __restrict__ vp,
            float* __restrict__ part, float* __restrict__ nnp) {
    int split = blockIdx.x, bh = blockIdx.y;
    __shared__ float Ks[32][128];
    __shared__ float Vs[32][128];
    int tid = threadIdx.x;
    int tx = tid & 15, ty = tid >> 4;
    float acc[8][8] = {};
    float colsum = 0.f;
    long base = ((long)bh*SEQ + split*128)*DH;
    for (int c = 0; c < 4; ++c) {
        for (int idx = tid; idx < 32*128; idx += 256) {
            int r = idx >> 7, col = idx & 127;
            long off = base + (long)(c*32 + r)*DH + col;
            Ks[r][col] = ke[off];
            Vs[r][col] = vp[off];
        }
        __syncthreads();
        #pragma unroll
        for (int nn = 0; nn < 32; ++nn) {
            float a[8], b[8];
            #pragma unroll
            for (int u = 0; u < 8; ++u) a[u] = Ks[nn][ty*8+u];
            #pragma unroll
            for (int v = 0; v < 8; ++v) b[v] = Vs[nn][tx*8+v];
            #pragma unroll
            for (int u = 0; u < 8; ++u)
                #pragma unroll
                for (int v = 0; v < 8; ++v) acc[u][v] += a[u]*b[v];
        }
        // fused new_norm partial: column sums of ke tile (rows ascending, so
        // summation order matches the standalone kernel exactly)
        if (tid < 128) {
            #pragma unroll
            for (int r = 0; r < 32; ++r) colsum += Ks[r][tid];
        }
        __syncthreads();
    }
    float* pg = part + ((long)(split*BH + bh))*DH*DH;
    #pragma unroll
    for (int u = 0; u < 8; ++u)
        #pragma unroll
        for (int v = 0; v < 8; ++v)
            pg[(ty*8+u)*DH + tx*8+v] = acc[u][v];
    if (tid < 128) nnp[(bh*16 + split)*DH + tid] = colsum;
}

__global__ void nkv_reduce(const float* __restrict__ part,
                           const float* __restrict__ pkv,
                           float* __restrict__ out) {
    int bh = blockIdx.y;
    int e = blockIdx.x*256 + threadIdx.x;
    float s = pkv[(long)bh*DH*DH + e];
    #pragma unroll
    for (int sp = 0; sp < 16; ++sp)
        s += part[((long)(sp*BH + bh))*DH*DH + e];
    out[(long)bh*DH*DH + e] = s;
}

__global__ void nnorm_reduce(const float* __restrict__ part,
                             const float* __restrict__ pnorm,
                             float* __restrict__ out) {
    int bh = blockIdx.x, k = threadIdx.x;
    float s = pnorm[bh*DH + k];
    #pragma unroll
    for (int c = 0; c < 16; ++c) s += part[(bh*16 + c)*DH + k];
    out[bh*DH + k] = s;
}

// ---------------- launch ----------------
extern "C" void kernel_launch(void* const* d_in, const int* in_sizes, int n_in,
                              void* d_out, int out_size) {
    const float* x          = (const float*)d_in[0];
    const float* gamma      = (const float*)d_in[1];
    const float* w_qkv      = (const float*)d_in[2];
    const float* w_out      = (const float*)d_in[3];
    const float* head_gates = (const float*)d_in[4];
    const float* past_kv    = (const float*)d_in[5];
    const float* past_norm  = (const float*)d_in[6];
    float* out = (float*)d_out;

    float *xn, *qkv, *q, *k, *v, *qe, *ke, *vp, *att, *mo, *dv, *comb, *nkvp, *nnp, *freq;
    cudaGetSymbolAddress((void**)&xn,   g_xn);
    cudaGetSymbolAddress((void**)&qkv,  g_qkv);
    cudaGetSymbolAddress((void**)&q,    g_q);
    cudaGetSymbolAddress((void**)&k,    g_k);
    cudaGetSymbolAddress((void**)&v,    g_v);
    cudaGetSymbolAddress((void**)&qe,   g_qe);
    cudaGetSymbolAddress((void**)&ke,   g_ke);
    cudaGetSymbolAddress((void**)&vp,   g_vp);
    cudaGetSymbolAddress((void**)&att,  g_att);
    cudaGetSymbolAddress((void**)&mo,   g_mo);
    cudaGetSymbolAddress((void**)&dv,   g_dv);
    cudaGetSymbolAddress((void**)&comb, g_comb);
    cudaGetSymbolAddress((void**)&nkvp, g_nkv_part);
    cudaGetSymbolAddress((void**)&nnp,  g_nn_part);
    cudaGetSymbolAddress((void**)&freq, g_freq);

    // idempotent, deterministic; safe on every call
    cudaFuncSetAttribute(flash_kernel,
                         cudaFuncAttributeMaxDynamicSharedMemorySize, FL_SMEM);

    // 1. L2 normalize + gamma scale; RoPE freq table
    norm_kernel<<<ROWS, 256>>>(x, gamma, xn);
    freq_kernel<<<1, 64>>>(freq);

    // 2. qkv = xn @ w_qkv (tf32)
    tfgemm_nn<<<dim3(QKVC/128, ROWS/128, 1), 256>>>(xn, w_qkv, qkv,
        QKVC, DIM, 0, 0, 0);

    // 3. split/scale/RoPE/elu
    transform_kernel<<<ROWS, 256>>>(qkv, freq, q, k, v, qe, ke);

    // 4-6. fused flash attention (R12 config)
    flash_kernel<<<dim3(32, BH), 256, FL_SMEM>>>(q, k, v, att);

    // 7-8. fused mem_out + delta_v GEMMs
    memdv_kernel<<<dim3(1, SEQ/128, BH*2), 256>>>(qe, ke, past_kv, mo, dv);

    // 9-10. fused blend + vprime
    blendv_kernel<<<(BH*SEQ*32 + 255)/256, 256>>>(qe, ke, att, mo, v, dv,
                                                  past_norm, head_gates, comb, vp);

    // 11. new_kv split-K (+ fused new_norm partials), then reduces
    nkv_partial<<<dim3(16, BH), 256>>>(ke, vp, nkvp, nnp);
    nkv_reduce<<<dim3(DH*DH/256, BH), 256>>>(nkvp, past_kv, out + NKV_OFF);
    nnorm_reduce<<<BH, 128>>>(nnp, past_norm, out + NNORM_OFF);

    // 12. final projection (tf32): out = comb @ w_out
    tfgemm_nn<<<dim3(DIM/128, ROWS/128, 1), 256>>>(comb, w_out, out + OUT_OFF,
        DIM, DIM, 0, 0, 0);
}